// round 1
// baseline (speedup 1.0000x reference)
#include <cuda_runtime.h>
#include <math.h>
#include <math_constants.h>

#define NN 100000
#define DD 64
#define HH 128
#define EE 500000
#define BB 8192

// ---------------- scratch (device globals; no allocation allowed) ----------
__device__ float g_feat[NN * DD];          // 25.6 MB, reused per (type, metapath)
__device__ float g_z[4][NN * DD];          // [type*2 + m], 102.4 MB
__device__ float g_el[NN];
__device__ float g_er[NN];
__device__ float g_mx[NN];
__device__ float g_den[NN];
__device__ float g_e[EE];                  // edge score -> exp(score - max)
__device__ float g_w[4];                   // semantic logits  [type*2+m]
__device__ float g_beta[4];                // semantic weights [type*2+m]

// ---------------- helpers ---------------------------------------------------
__device__ __forceinline__ void atomicMaxFloat(float* addr, float val) {
    if (val >= 0.0f) {
        atomicMax((int*)addr, __float_as_int(val));
    } else {
        atomicMin((unsigned int*)addr, __float_as_uint(val));
    }
}

// ---------------- K0: zero semantic logits ----------------------------------
__global__ void k_zero_w() {
    if (threadIdx.x < 4) g_w[threadIdx.x] = 0.0f;
}

// ---------------- K1: feat = h @ W ; el/er ; init mx/den ; zero z[slot] -----
// grid: ceil(NN/256) blocks of 256 threads; one row per thread.
// dyn smem: W (64x64) + al + ar + staged h rows (256 x 64, pad 65)
#define K1_SMEM ((4096 + 64 + 64 + 256 * 65) * 4)

__global__ void __launch_bounds__(256) k_gemm_feat(
    const float* __restrict__ h, const float* __restrict__ W,
    const float* __restrict__ al, const float* __restrict__ ar, int slot)
{
    extern __shared__ float smem[];
    float* Ws  = smem;          // 4096
    float* als = Ws + 4096;     // 64
    float* ars = als + 64;      // 64
    float* hs  = ars + 64;      // 256*65

    int tid  = threadIdx.x;
    int row0 = blockIdx.x * 256;

    for (int i = tid; i < 4096; i += 256) Ws[i] = W[i];
    if (tid < 64) { als[tid] = al[tid]; ars[tid] = ar[tid]; }

    int nrows = NN - row0; if (nrows > 256) nrows = 256;
    for (int i = tid; i < nrows * 64; i += 256)
        hs[(i >> 6) * 65 + (i & 63)] = h[(size_t)row0 * 64 + i];
    __syncthreads();

    int row = row0 + tid;
    if (row >= NN) return;

    float acc[64];
#pragma unroll
    for (int d = 0; d < 64; d++) acc[d] = 0.0f;

    const float* hrow = &hs[tid * 65];
    for (int k = 0; k < 64; k++) {
        float hv = hrow[k];
        const float4* Wk = (const float4*)&Ws[k * 64];
#pragma unroll
        for (int j = 0; j < 16; j++) {
            float4 w4 = Wk[j];
            acc[4 * j + 0] += hv * w4.x;
            acc[4 * j + 1] += hv * w4.y;
            acc[4 * j + 2] += hv * w4.z;
            acc[4 * j + 3] += hv * w4.w;
        }
    }

    float e_l = 0.0f, e_r = 0.0f;
#pragma unroll
    for (int d = 0; d < 64; d++) { e_l += acc[d] * als[d]; e_r += acc[d] * ars[d]; }
    g_el[row] = e_l;
    g_er[row] = e_r;
    g_mx[row] = -CUDART_INF_F;
    g_den[row] = 0.0f;

    float4* fout = (float4*)&g_feat[(size_t)row * 64];
    float4* zout = (float4*)&g_z[slot][(size_t)row * 64];
    float4 z4 = make_float4(0.f, 0.f, 0.f, 0.f);
#pragma unroll
    for (int j = 0; j < 16; j++) {
        fout[j] = make_float4(acc[4 * j + 0], acc[4 * j + 1],
                              acc[4 * j + 2], acc[4 * j + 3]);
        zout[j] = z4;
    }
}

// ---------------- K2: edge score + segment max ------------------------------
__global__ void k_edge_max(const int* __restrict__ src, const int* __restrict__ dst)
{
    int i = blockIdx.x * blockDim.x + threadIdx.x;
    if (i >= EE) return;
    int s = src[i], d = dst[i];
    float e = g_el[s] + g_er[d];
    e = (e >= 0.0f) ? e : 0.2f * e;          // leaky_relu 0.2
    g_e[i] = e;
    atomicMaxFloat(&g_mx[d], e);
}

// ---------------- K3: exp + segment sum (denominator) -----------------------
__global__ void k_edge_exp(const int* __restrict__ dst)
{
    int i = blockIdx.x * blockDim.x + threadIdx.x;
    if (i >= EE) return;
    int d = dst[i];
    float ex = expf(g_e[i] - g_mx[d]);
    g_e[i] = ex;
    atomicAdd(&g_den[d], ex);
}

// ---------------- K4: alpha * feat[src] scatter-add into z[slot] ------------
// 16 threads per edge, each handles one float4 chunk (16*16B = 256B row).
__global__ void __launch_bounds__(256) k_edge_aggr(
    const int* __restrict__ src, const int* __restrict__ dst, int slot)
{
    int t = blockIdx.x * 256 + threadIdx.x;
    int edge = t >> 4;
    int lane = t & 15;
    if (edge >= EE) return;
    int s = src[edge], d = dst[edge];
    float alpha = g_e[edge] / (g_den[d] + 1e-9f);
    float4 f = *(const float4*)&g_feat[(size_t)s * 64 + lane * 4];
    float4 v = make_float4(f.x * alpha, f.y * alpha, f.z * alpha, f.w * alpha);
    float* zp = &g_z[slot][(size_t)d * 64 + lane * 4];
    asm volatile("red.global.add.v4.f32 [%0], {%1,%2,%3,%4};"
                 :: "l"(zp), "f"(v.x), "f"(v.y), "f"(v.z), "f"(v.w)
                 : "memory");
}

// ---------------- K5: z = elu(z + b) ----------------------------------------
__global__ void k_elu_bias(int slot, const float* __restrict__ b)
{
    int i = blockIdx.x * blockDim.x + threadIdx.x;   // over NN*16 float4s
    if (i >= NN * 16) return;
    float4* zp = (float4*)&g_z[slot][(size_t)i * 4];
    float4 v = *zp;
    int d = (i * 4) & 63;
    v.x += b[d + 0]; v.y += b[d + 1]; v.z += b[d + 2]; v.w += b[d + 3];
    v.x = (v.x > 0.f) ? v.x : expm1f(v.x);
    v.y = (v.y > 0.f) ? v.y : expm1f(v.y);
    v.z = (v.z > 0.f) ? v.z : expm1f(v.z);
    v.w = (v.w > 0.f) ? v.w : expm1f(v.w);
    *zp = v;
}

// ---------------- K6: semantic attention logits -----------------------------
// sum_n tanh(z @ W1 + b1) @ W2 for both metapaths of one type.
// 128 threads = one per hidden unit; W1 column cached in registers.
__global__ void __launch_bounds__(128) k_sem_score(
    int t, const float* __restrict__ W1, const float* __restrict__ b1,
    const float* __restrict__ W2)
{
    __shared__ __align__(16) float zs0[64];
    __shared__ __align__(16) float zs1[64];
    __shared__ float redbuf[8];

    int h = threadIdx.x;
    const float* z0 = g_z[2 * t];
    const float* z1 = g_z[2 * t + 1];

    float w1c[64];
#pragma unroll
    for (int k = 0; k < 64; k++) w1c[k] = W1[(size_t)k * 128 + h];
    float bh = b1[h];

    float s0 = 0.0f, s1 = 0.0f;
    int per = (NN + gridDim.x - 1) / gridDim.x;
    int r0 = blockIdx.x * per;
    int r1 = r0 + per; if (r1 > NN) r1 = NN;

    for (int r = r0; r < r1; r++) {
        if (h < 64) zs0[h] = z0[(size_t)r * 64 + h];
        else        zs1[h - 64] = z1[(size_t)r * 64 + (h - 64)];
        __syncthreads();
        float a0 = bh, a1 = bh;
        const float4* p0 = (const float4*)zs0;
        const float4* p1 = (const float4*)zs1;
#pragma unroll
        for (int k4 = 0; k4 < 16; k4++) {
            float4 x0 = p0[k4];
            float4 x1 = p1[k4];
            a0 += x0.x * w1c[4 * k4 + 0] + x0.y * w1c[4 * k4 + 1]
                + x0.z * w1c[4 * k4 + 2] + x0.w * w1c[4 * k4 + 3];
            a1 += x1.x * w1c[4 * k4 + 0] + x1.y * w1c[4 * k4 + 1]
                + x1.z * w1c[4 * k4 + 2] + x1.w * w1c[4 * k4 + 3];
        }
        s0 += tanhf(a0);
        s1 += tanhf(a1);
        __syncthreads();
    }

    float v2 = W2[h];
    s0 *= v2; s1 *= v2;
#pragma unroll
    for (int off = 16; off > 0; off >>= 1) {
        s0 += __shfl_xor_sync(0xffffffffu, s0, off);
        s1 += __shfl_xor_sync(0xffffffffu, s1, off);
    }
    int w = h >> 5;
    if ((h & 31) == 0) { redbuf[w] = s0; redbuf[4 + w] = s1; }
    __syncthreads();
    if (h == 0) {
        float t0 = redbuf[0] + redbuf[1] + redbuf[2] + redbuf[3];
        float t1 = redbuf[4] + redbuf[5] + redbuf[6] + redbuf[7];
        atomicAdd(&g_w[2 * t + 0], t0);
        atomicAdd(&g_w[2 * t + 1], t1);
    }
}

// ---------------- K7: beta = softmax(w / NN) over metapaths -----------------
__global__ void k_beta()
{
    if (threadIdx.x != 0 || blockIdx.x != 0) return;
    for (int t = 0; t < 2; t++) {
        float w0 = g_w[2 * t] * (1.0f / NN);
        float w1 = g_w[2 * t + 1] * (1.0f / NN);
        float m = fmaxf(w0, w1);
        float e0 = expf(w0 - m), e1 = expf(w1 - m);
        float inv = 1.0f / (e0 + e1);
        g_beta[2 * t + 0] = e0 * inv;
        g_beta[2 * t + 1] = e1 * inv;
    }
}

// ---------------- K8: gather + beta-combine + GEMM + ReLU + LayerNorm -------
// Only for the 3*B gathered rows. 4 rows/block, 64 threads/row.
__global__ void __launch_bounds__(256) k_final(
    const int* __restrict__ user_idx, const int* __restrict__ item_idx,
    const int* __restrict__ neg_idx,
    const float* __restrict__ userW, const float* __restrict__ userb,
    const float* __restrict__ itemW, const float* __restrict__ itemb,
    const float* __restrict__ ln_g, const float* __restrict__ ln_b,
    float* __restrict__ out)
{
    __shared__ float Ws[4096];
    __shared__ float bs[64], gs[64], lbs[64];
    __shared__ float embs[4][64];
    __shared__ float red[4][2];

    int tid = threadIdx.x;
    int tx = tid & 63, ty = tid >> 6;
    int r0 = blockIdx.x * 4;
    bool isUser = (r0 < BB);                 // BB multiple of 4 -> uniform per block
    const float* W    = isUser ? userW : itemW;
    const float* bias = isUser ? userb : itemb;

    for (int i = tid; i < 4096; i += 256) Ws[i] = W[i];
    if (tid < 64) { bs[tid] = bias[tid]; gs[tid] = ln_g[tid]; lbs[tid] = ln_b[tid]; }

    int r = r0 + ty;
    int type, idx;
    if (r < BB)            { type = 0; idx = user_idx[r]; }
    else if (r < 2 * BB)   { type = 1; idx = item_idx[r - BB]; }
    else                   { type = 1; idx = neg_idx[r - 2 * BB]; }

    float b0 = g_beta[2 * type], b1 = g_beta[2 * type + 1];
    float emb = b0 * g_z[2 * type][(size_t)idx * 64 + tx]
              + b1 * g_z[2 * type + 1][(size_t)idx * 64 + tx];
    embs[ty][tx] = emb;
    __syncthreads();

    float y = bs[tx];
#pragma unroll 16
    for (int k = 0; k < 64; k++) y += embs[ty][k] * Ws[k * 64 + tx];
    y = fmaxf(y, 0.0f);

    // layernorm over 64 lanes (2 warps per row)
    float s = y;
#pragma unroll
    for (int off = 16; off > 0; off >>= 1) s += __shfl_xor_sync(0xffffffffu, s, off);
    int half = tx >> 5;
    if ((tx & 31) == 0) red[ty][half] = s;
    __syncthreads();
    float mu = (red[ty][0] + red[ty][1]) * (1.0f / 64.0f);
    float dv = y - mu;
    float s2 = dv * dv;
#pragma unroll
    for (int off = 16; off > 0; off >>= 1) s2 += __shfl_xor_sync(0xffffffffu, s2, off);
    __syncthreads();
    if ((tx & 31) == 0) red[ty][half] = s2;
    __syncthreads();
    float var = (red[ty][0] + red[ty][1]) * (1.0f / 64.0f);
    float o = gs[tx] * dv * rsqrtf(var + 1e-5f) + lbs[tx];
    out[(size_t)r * 64 + tx] = o;
}

// ---------------- host ------------------------------------------------------
extern "C" void kernel_launch(void* const* d_in, const int* in_sizes, int n_in,
                              void* d_out, int out_size)
{
    const int*   user_idx  = (const int*)d_in[0];
    const int*   item_idx  = (const int*)d_in[1];
    const int*   neg_idx   = (const int*)d_in[2];
    const float* user_feat = (const float*)d_in[3];
    const float* item_feat = (const float*)d_in[4];
    const int*   u_src = (const int*)d_in[5];
    const int*   u_dst = (const int*)d_in[6];
    const int*   i_src = (const int*)d_in[7];
    const int*   i_dst = (const int*)d_in[8];
    const float* u_W  = (const float*)d_in[9];
    const float* u_al = (const float*)d_in[10];
    const float* u_ar = (const float*)d_in[11];
    const float* u_b  = (const float*)d_in[12];
    const float* i_W  = (const float*)d_in[13];
    const float* i_al = (const float*)d_in[14];
    const float* i_ar = (const float*)d_in[15];
    const float* i_b  = (const float*)d_in[16];
    const float* u_saW1 = (const float*)d_in[17];
    const float* u_sab1 = (const float*)d_in[18];
    const float* u_saW2 = (const float*)d_in[19];
    const float* i_saW1 = (const float*)d_in[20];
    const float* i_sab1 = (const float*)d_in[21];
    const float* i_saW2 = (const float*)d_in[22];
    const float* userW = (const float*)d_in[23];
    const float* userb = (const float*)d_in[24];
    const float* itemW = (const float*)d_in[25];
    const float* itemb = (const float*)d_in[26];
    const float* ln_g  = (const float*)d_in[27];
    const float* ln_b  = (const float*)d_in[28];
    float* out = (float*)d_out;

    cudaFuncSetAttribute(k_gemm_feat,
                         cudaFuncAttributeMaxDynamicSharedMemorySize, K1_SMEM);

    k_zero_w<<<1, 32>>>();

    const float* feats[2] = {user_feat, item_feat};
    const int*   srcs[2]  = {u_src, i_src};
    const int*   dsts[2]  = {u_dst, i_dst};
    const float* Wms[2]   = {u_W, i_W};
    const float* als[2]   = {u_al, i_al};
    const float* ars[2]   = {u_ar, i_ar};
    const float* bms[2]   = {u_b, i_b};

    const int grid1 = (NN + 255) / 256;          // 391
    const int gridE = (EE + 255) / 256;          // 1954
    const int gridA = (EE * 16) / 256;           // 31250
    const int gridZ = (NN * 16 + 255) / 256;     // 6250

    for (int t = 0; t < 2; t++) {
        for (int m = 0; m < 2; m++) {
            int slot = 2 * t + m;
            k_gemm_feat<<<grid1, 256, K1_SMEM>>>(feats[t], Wms[t] + m * 4096,
                                                 als[t] + m * 64, ars[t] + m * 64, slot);
            k_edge_max<<<gridE, 256>>>(srcs[t] + m * EE, dsts[t] + m * EE);
            k_edge_exp<<<gridE, 256>>>(dsts[t] + m * EE);
            k_edge_aggr<<<gridA, 256>>>(srcs[t] + m * EE, dsts[t] + m * EE, slot);
            k_elu_bias<<<gridZ, 256>>>(slot, bms[t] + m * 64);
        }
    }

    k_sem_score<<<1024, 128>>>(0, u_saW1, u_sab1, u_saW2);
    k_sem_score<<<1024, 128>>>(1, i_saW1, i_sab1, i_saW2);
    k_beta<<<1, 1>>>();
    k_final<<<(3 * BB) / 4, 256>>>(user_idx, item_idx, neg_idx,
                                   userW, userb, itemW, itemb, ln_g, ln_b, out);
}

// round 3
// speedup vs baseline: 1.3328x; 1.3328x over previous
#include <cuda_runtime.h>
#include <math.h>

#define NN 100000
#define EE 500000
#define BB 8192

// ---------------- scratch (device globals) ----------------------------------
__device__ float g_feat[NN * 64];
__device__ float g_z[4][NN * 64];
__device__ float g_el[NN];
__device__ float g_er[NN];
__device__ float g_den[NN];
__device__ float g_e[EE];
__device__ float g_w[4];
__device__ float g_beta[4];

typedef unsigned long long u64t;

// ---------------- packed f32x2 helpers (sm_100) ------------------------------
__device__ __forceinline__ u64t ffma2(u64t a, u64t b, u64t c) {
    u64t d;
    asm("fma.rn.f32x2 %0, %1, %2, %3;" : "=l"(d) : "l"(a), "l"(b), "l"(c));
    return d;
}
__device__ __forceinline__ u64t pack2(float lo, float hi) {
    u64t r; asm("mov.b64 %0, {%1,%2};" : "=l"(r) : "f"(lo), "f"(hi)); return r;
}
__device__ __forceinline__ void unpack2(u64t v, float& lo, float& hi) {
    asm("mov.b64 {%0,%1}, %2;" : "=f"(lo), "=f"(hi) : "l"(v));
}
__device__ __forceinline__ float tanh_fast(float x) {
    float y; asm("tanh.approx.f32 %0, %1;" : "=f"(y) : "f"(x)); return y;
}
__device__ __forceinline__ float elu_fast(float x) {
    return x > 0.f ? x : (__expf(x) - 1.f);
}

// ---------------- K0: zero semantic logits ----------------------------------
__global__ void k_zero_w() {
    if (threadIdx.x < 4) g_w[threadIdx.x] = 0.0f;
}

// ---------------- K1: feat = h @ W ; el/er ; init den ; zero z[slot] --------
#define K1_SMEM ((4096 + 64 + 64 + 256 * 65) * 4)

__global__ void __launch_bounds__(256) k_gemm_feat(
    const float* __restrict__ h, const float* __restrict__ W,
    const float* __restrict__ al, const float* __restrict__ ar, int slot)
{
    extern __shared__ float smem[];
    float* Ws  = smem;          // 4096 (16B aligned)
    float* als = Ws + 4096;     // 64
    float* ars = als + 64;      // 64
    float* hs  = ars + 64;      // 256*65

    int tid  = threadIdx.x;
    int row0 = blockIdx.x * 256;

    for (int i = tid; i < 4096; i += 256) Ws[i] = W[i];
    if (tid < 64) { als[tid] = al[tid]; ars[tid] = ar[tid]; }

    int nrows = NN - row0; if (nrows > 256) nrows = 256;
    for (int i = tid; i < nrows * 64; i += 256)
        hs[(i >> 6) * 65 + (i & 63)] = h[(size_t)row0 * 64 + i];
    __syncthreads();

    int row = row0 + tid;
    if (row >= NN) return;

    u64t acc2[32];
#pragma unroll
    for (int j = 0; j < 32; j++) acc2[j] = 0ull;

    const float* hrow = &hs[tid * 65];
#pragma unroll 4
    for (int k = 0; k < 64; k++) {
        float hv = hrow[k];
        u64t hv2 = pack2(hv, hv);
        const ulonglong2* Wk = (const ulonglong2*)&Ws[k * 64];
#pragma unroll
        for (int j = 0; j < 16; j++) {
            ulonglong2 w = Wk[j];
            acc2[2 * j + 0] = ffma2(hv2, w.x, acc2[2 * j + 0]);
            acc2[2 * j + 1] = ffma2(hv2, w.y, acc2[2 * j + 1]);
        }
    }

    float e_l = 0.0f, e_r = 0.0f;
    float4* fout = (float4*)&g_feat[(size_t)row * 64];
    float4* zout = (float4*)&g_z[slot][(size_t)row * 64];
    float4 z4 = make_float4(0.f, 0.f, 0.f, 0.f);
#pragma unroll
    for (int i = 0; i < 16; i++) {
        float a0, a1, a2, a3;
        unpack2(acc2[2 * i + 0], a0, a1);
        unpack2(acc2[2 * i + 1], a2, a3);
        e_l += a0 * als[4 * i + 0] + a1 * als[4 * i + 1]
             + a2 * als[4 * i + 2] + a3 * als[4 * i + 3];
        e_r += a0 * ars[4 * i + 0] + a1 * ars[4 * i + 1]
             + a2 * ars[4 * i + 2] + a3 * ars[4 * i + 3];
        fout[i] = make_float4(a0, a1, a2, a3);
        zout[i] = z4;
    }
    g_el[row] = e_l;
    g_er[row] = e_r;
    g_den[row] = 0.0f;
}

// ---------------- K2: fused edge score + exp + segment sum ------------------
// No max subtraction: softmax is shift-invariant; scores are O(+-5) so exp is safe.
__global__ void k_edge_score(const int* __restrict__ src, const int* __restrict__ dst)
{
    int i = blockIdx.x * blockDim.x + threadIdx.x;
    if (i >= EE) return;
    int s = src[i], d = dst[i];
    float e = g_el[s] + g_er[d];
    e = (e >= 0.0f) ? e : 0.2f * e;          // leaky_relu 0.2
    float ex = __expf(e);
    g_e[i] = ex;
    atomicAdd(&g_den[d], ex);
}

// ---------------- K3: alpha * feat[src] scatter-add into z[slot] ------------
__global__ void __launch_bounds__(256) k_edge_aggr(
    const int* __restrict__ src, const int* __restrict__ dst, int slot)
{
    int t = blockIdx.x * 256 + threadIdx.x;
    int edge = t >> 4;
    int lane = t & 15;
    if (edge >= EE) return;
    int s = src[edge], d = dst[edge];
    float alpha = g_e[edge] / (g_den[d] + 1e-9f);
    float4 f = *(const float4*)&g_feat[(size_t)s * 64 + lane * 4];
    float4 v = make_float4(f.x * alpha, f.y * alpha, f.z * alpha, f.w * alpha);
    float* zp = &g_z[slot][(size_t)d * 64 + lane * 4];
    asm volatile("red.global.add.v4.f32 [%0], {%1,%2,%3,%4};"
                 :: "l"(zp), "f"(v.x), "f"(v.y), "f"(v.z), "f"(v.w)
                 : "memory");
}

// ---------------- K4: semantic attention logits (both types via blockIdx.y) --
__global__ void __launch_bounds__(128) k_sem(
    const float* __restrict__ uW1, const float* __restrict__ ub1,
    const float* __restrict__ uW2, const float* __restrict__ ugb,
    const float* __restrict__ iW1, const float* __restrict__ ib1,
    const float* __restrict__ iW2, const float* __restrict__ igb)
{
    __shared__ __align__(16) float zs0[4][64];
    __shared__ __align__(16) float zs1[4][64];
    __shared__ float bsh[128];     // [metapath0 64 | metapath1 64]
    __shared__ float redbuf[8];

    int t = blockIdx.y;
    const float* W1 = t ? iW1 : uW1;
    const float* b1 = t ? ib1 : ub1;
    const float* W2 = t ? iW2 : uW2;
    const float* gb = t ? igb : ugb;
    const float* z0 = g_z[2 * t];
    const float* z1 = g_z[2 * t + 1];

    int h = threadIdx.x;
    bsh[h] = gb[h];

    // W1 column h, packed into 32 f32x2 pairs (consecutive k)
    u64t wpair[32];
#pragma unroll
    for (int k2 = 0; k2 < 32; k2++)
        wpair[k2] = pack2(W1[(size_t)(2 * k2) * 128 + h],
                          W1[(size_t)(2 * k2 + 1) * 128 + h]);
    float bh = b1[h];

    int r = h >> 5;          // staging row 0..3
    int c2 = h & 31;         // staging float2 index

    float s0 = 0.0f, s1 = 0.0f;
    const int NCHUNK = NN / 4;   // 25000
    for (int c = blockIdx.x; c < NCHUNK; c += gridDim.x) {
        int row = c * 4 + r;
        float2 p0 = ((const float2*)(z0 + (size_t)row * 64))[c2];
        float2 p1 = ((const float2*)(z1 + (size_t)row * 64))[c2];
        __syncthreads();   // previous chunk's compute done before overwrite
        zs0[r][2 * c2 + 0] = elu_fast(p0.x + bsh[2 * c2 + 0]);
        zs0[r][2 * c2 + 1] = elu_fast(p0.y + bsh[2 * c2 + 1]);
        zs1[r][2 * c2 + 0] = elu_fast(p1.x + bsh[64 + 2 * c2 + 0]);
        zs1[r][2 * c2 + 1] = elu_fast(p1.y + bsh[64 + 2 * c2 + 1]);
        __syncthreads();

#pragma unroll
        for (int rr = 0; rr < 4; rr++) {
            u64t a0 = 0ull, a1 = 0ull;
            const ulonglong2* q0 = (const ulonglong2*)zs0[rr];
            const ulonglong2* q1 = (const ulonglong2*)zs1[rr];
#pragma unroll
            for (int j = 0; j < 16; j++) {
                ulonglong2 x0 = q0[j];
                ulonglong2 x1 = q1[j];
                a0 = ffma2(x0.x, wpair[2 * j + 0], a0);
                a0 = ffma2(x0.y, wpair[2 * j + 1], a0);
                a1 = ffma2(x1.x, wpair[2 * j + 0], a1);
                a1 = ffma2(x1.y, wpair[2 * j + 1], a1);
            }
            float l0, h0, l1, h1;
            unpack2(a0, l0, h0);
            unpack2(a1, l1, h1);
            s0 += tanh_fast(l0 + h0 + bh);
            s1 += tanh_fast(l1 + h1 + bh);
        }
    }

    float v2 = W2[h];
    s0 *= v2; s1 *= v2;
#pragma unroll
    for (int off = 16; off > 0; off >>= 1) {
        s0 += __shfl_xor_sync(0xffffffffu, s0, off);
        s1 += __shfl_xor_sync(0xffffffffu, s1, off);
    }
    int w = h >> 5;
    if ((h & 31) == 0) { redbuf[w] = s0; redbuf[4 + w] = s1; }
    __syncthreads();
    if (h == 0) {
        float t0 = redbuf[0] + redbuf[1] + redbuf[2] + redbuf[3];
        float t1 = redbuf[4] + redbuf[5] + redbuf[6] + redbuf[7];
        atomicAdd(&g_w[2 * t + 0], t0);
        atomicAdd(&g_w[2 * t + 1], t1);
    }
}

// ---------------- K5: beta = softmax(w / NN) over metapaths -----------------
__global__ void k_beta()
{
    if (threadIdx.x != 0 || blockIdx.x != 0) return;
    for (int t = 0; t < 2; t++) {
        float w0 = g_w[2 * t] * (1.0f / NN);
        float w1 = g_w[2 * t + 1] * (1.0f / NN);
        float m = fmaxf(w0, w1);
        float e0 = __expf(w0 - m), e1 = __expf(w1 - m);
        float inv = 1.0f / (e0 + e1);
        g_beta[2 * t + 0] = e0 * inv;
        g_beta[2 * t + 1] = e1 * inv;
    }
}

// ---------------- K6: gather + bias/ELU + beta-combine + GEMM + ReLU + LN ----
__global__ void __launch_bounds__(256) k_final(
    const int* __restrict__ user_idx, const int* __restrict__ item_idx,
    const int* __restrict__ neg_idx,
    const float* __restrict__ u_gb, const float* __restrict__ i_gb,
    const float* __restrict__ userW, const float* __restrict__ userb,
    const float* __restrict__ itemW, const float* __restrict__ itemb,
    const float* __restrict__ ln_g, const float* __restrict__ ln_b,
    float* __restrict__ out)
{
    __shared__ float Ws[4096];
    __shared__ float bs[64], gs[64], lbs[64];
    __shared__ float gb0[64], gb1[64];
    __shared__ float embs[4][64];
    __shared__ float red[4][2];

    int tid = threadIdx.x;
    int tx = tid & 63, ty = tid >> 6;
    int r0 = blockIdx.x * 4;
    bool isUser = (r0 < BB);                 // uniform per block (BB % 4 == 0)
    const float* W    = isUser ? userW : itemW;
    const float* bias = isUser ? userb : itemb;
    const float* gbm  = isUser ? u_gb : i_gb;

    for (int i = tid; i < 4096; i += 256) Ws[i] = W[i];
    if (tid < 64) {
        bs[tid] = bias[tid]; gs[tid] = ln_g[tid]; lbs[tid] = ln_b[tid];
        gb0[tid] = gbm[tid]; gb1[tid] = gbm[64 + tid];
    }

    int r = r0 + ty;
    int type, idx;
    if (r < BB)            { type = 0; idx = user_idx[r]; }
    else if (r < 2 * BB)   { type = 1; idx = item_idx[r - BB]; }
    else                   { type = 1; idx = neg_idx[r - 2 * BB]; }

    float b0 = g_beta[2 * type], b1 = g_beta[2 * type + 1];
    __syncthreads();
    float zr0 = g_z[2 * type][(size_t)idx * 64 + tx] + gb0[tx];
    float zr1 = g_z[2 * type + 1][(size_t)idx * 64 + tx] + gb1[tx];
    float emb = b0 * elu_fast(zr0) + b1 * elu_fast(zr1);
    embs[ty][tx] = emb;
    __syncthreads();

    float y = bs[tx];
#pragma unroll 16
    for (int k = 0; k < 64; k++) y += embs[ty][k] * Ws[k * 64 + tx];
    y = fmaxf(y, 0.0f);

    float s = y;
#pragma unroll
    for (int off = 16; off > 0; off >>= 1) s += __shfl_xor_sync(0xffffffffu, s, off);
    int half = tx >> 5;
    if ((tx & 31) == 0) red[ty][half] = s;
    __syncthreads();
    float mu = (red[ty][0] + red[ty][1]) * (1.0f / 64.0f);
    float dv = y - mu;
    float s2 = dv * dv;
#pragma unroll
    for (int off = 16; off > 0; off >>= 1) s2 += __shfl_xor_sync(0xffffffffu, s2, off);
    __syncthreads();
    if ((tx & 31) == 0) red[ty][half] = s2;
    __syncthreads();
    float var = (red[ty][0] + red[ty][1]) * (1.0f / 64.0f);
    float o = gs[tx] * dv * rsqrtf(var + 1e-5f) + lbs[tx];
    out[(size_t)r * 64 + tx] = o;
}

// ---------------- host ------------------------------------------------------
extern "C" void kernel_launch(void* const* d_in, const int* in_sizes, int n_in,
                              void* d_out, int out_size)
{
    const int*   user_idx  = (const int*)d_in[0];
    const int*   item_idx  = (const int*)d_in[1];
    const int*   neg_idx   = (const int*)d_in[2];
    const float* user_feat = (const float*)d_in[3];
    const float* item_feat = (const float*)d_in[4];
    const int*   u_src = (const int*)d_in[5];
    const int*   u_dst = (const int*)d_in[6];
    const int*   i_src = (const int*)d_in[7];
    const int*   i_dst = (const int*)d_in[8];
    const float* u_W  = (const float*)d_in[9];
    const float* u_al = (const float*)d_in[10];
    const float* u_ar = (const float*)d_in[11];
    const float* u_b  = (const float*)d_in[12];
    const float* i_W  = (const float*)d_in[13];
    const float* i_al = (const float*)d_in[14];
    const float* i_ar = (const float*)d_in[15];
    const float* i_b  = (const float*)d_in[16];
    const float* u_saW1 = (const float*)d_in[17];
    const float* u_sab1 = (const float*)d_in[18];
    const float* u_saW2 = (const float*)d_in[19];
    const float* i_saW1 = (const float*)d_in[20];
    const float* i_sab1 = (const float*)d_in[21];
    const float* i_saW2 = (const float*)d_in[22];
    const float* userW = (const float*)d_in[23];
    const float* userb = (const float*)d_in[24];
    const float* itemW = (const float*)d_in[25];
    const float* itemb = (const float*)d_in[26];
    const float* ln_g  = (const float*)d_in[27];
    const float* ln_b  = (const float*)d_in[28];
    float* out = (float*)d_out;

    cudaFuncSetAttribute(k_gemm_feat,
                         cudaFuncAttributeMaxDynamicSharedMemorySize, K1_SMEM);

    k_zero_w<<<1, 32>>>();

    const float* feats[2] = {user_feat, item_feat};
    const int*   srcs[2]  = {u_src, i_src};
    const int*   dsts[2]  = {u_dst, i_dst};
    const float* Wms[2]   = {u_W, i_W};
    const float* als[2]   = {u_al, i_al};
    const float* ars[2]   = {u_ar, i_ar};

    const int grid1 = (NN + 255) / 256;          // 391
    const int gridE = (EE + 255) / 256;          // 1954
    const int gridA = (EE * 16) / 256;           // 31250

    for (int t = 0; t < 2; t++) {
        for (int m = 0; m < 2; m++) {
            int slot = 2 * t + m;
            k_gemm_feat<<<grid1, 256, K1_SMEM>>>(feats[t], Wms[t] + m * 4096,
                                                 als[t] + m * 64, ars[t] + m * 64, slot);
            k_edge_score<<<gridE, 256>>>(srcs[t] + m * EE, dsts[t] + m * EE);
            k_edge_aggr<<<gridA, 256>>>(srcs[t] + m * EE, dsts[t] + m * EE, slot);
        }
    }

    dim3 semGrid(1024, 2);
    k_sem<<<semGrid, 128>>>(u_saW1, u_sab1, u_saW2, u_b,
                            i_saW1, i_sab1, i_saW2, i_b);
    k_beta<<<1, 1>>>();
    k_final<<<(3 * BB) / 4, 256>>>(user_idx, item_idx, neg_idx, u_b, i_b,
                                   userW, userb, itemW, itemb, ln_g, ln_b, out);
}

// round 4
// speedup vs baseline: 1.6180x; 1.2140x over previous
#include <cuda_runtime.h>
#include <cuda_bf16.h>
#include <math.h>

#define NN 100000
#define EE 500000
#define BB 8192

// ---------------- scratch (device globals) ----------------------------------
__device__ float g_feat[2][NN * 64];       // per metapath
__device__ float g_z[4][NN * 64];          // [type*2 + m]
__device__ float g_el[2][NN];
__device__ float g_er[2][NN];
__device__ float g_den[2][NN];
__device__ float g_e[2][EE];
__device__ float g_w[4];
__device__ float g_beta[4];

typedef unsigned long long u64t;

// ---------------- helpers ----------------------------------------------------
__device__ __forceinline__ u64t ffma2(u64t a, u64t b, u64t c) {
    u64t d;
    asm("fma.rn.f32x2 %0, %1, %2, %3;" : "=l"(d) : "l"(a), "l"(b), "l"(c));
    return d;
}
__device__ __forceinline__ u64t pack2(float lo, float hi) {
    u64t r; asm("mov.b64 %0, {%1,%2};" : "=l"(r) : "f"(lo), "f"(hi)); return r;
}
__device__ __forceinline__ void unpack2(u64t v, float& lo, float& hi) {
    asm("mov.b64 {%0,%1}, %2;" : "=f"(lo), "=f"(hi) : "l"(v));
}
__device__ __forceinline__ float tanh_fast(float x) {
    float y; asm("tanh.approx.f32 %0, %1;" : "=f"(y) : "f"(x)); return y;
}
__device__ __forceinline__ float elu_fast(float x) {
    return x > 0.f ? x : (__expf(x) - 1.f);
}
__device__ __forceinline__ __nv_bfloat162 u2bf(unsigned int u) {
    return *reinterpret_cast<__nv_bfloat162*>(&u);
}

// ---------------- K1: fused per-type feat GEMM (both metapaths) -------------
// h staged once; per m: feat = h@W[m], el/er, init den, zero z.
// smem: W[2][4096] + al[2][64] + ar[2][64] + hs[256*65]
#define K1_SMEM ((2 * 4096 + 2 * 64 + 2 * 64 + 256 * 65) * 4)

__global__ void __launch_bounds__(256) k_gemm_feat(
    const float* __restrict__ h, const float* __restrict__ W,
    const float* __restrict__ al, const float* __restrict__ ar, int type)
{
    extern __shared__ float smem[];
    float* Ws  = smem;            // 2*4096
    float* als = Ws + 8192;       // 2*64
    float* ars = als + 128;       // 2*64
    float* hs  = ars + 128;       // 256*65

    int tid  = threadIdx.x;
    int row0 = blockIdx.x * 256;

    if (type == 0 && blockIdx.x == 0 && tid < 4) g_w[tid] = 0.0f;

    for (int i = tid; i < 8192; i += 256) Ws[i] = W[i];
    if (tid < 128) { als[tid] = al[tid]; ars[tid] = ar[tid]; }

    int nrows = NN - row0; if (nrows > 256) nrows = 256;
    for (int i = tid; i < nrows * 64; i += 256)
        hs[(i >> 6) * 65 + (i & 63)] = h[(size_t)row0 * 64 + i];
    __syncthreads();

    int row = row0 + tid;
    if (row >= NN) return;
    const float* hrow = &hs[tid * 65];

#pragma unroll
    for (int m = 0; m < 2; m++) {
        u64t acc2[32];
#pragma unroll
        for (int j = 0; j < 32; j++) acc2[j] = 0ull;

        const float* Wm = Ws + m * 4096;
#pragma unroll 4
        for (int k = 0; k < 64; k++) {
            float hv = hrow[k];
            u64t hv2 = pack2(hv, hv);
            const ulonglong2* Wk = (const ulonglong2*)&Wm[k * 64];
#pragma unroll
            for (int j = 0; j < 16; j++) {
                ulonglong2 w = Wk[j];
                acc2[2 * j + 0] = ffma2(hv2, w.x, acc2[2 * j + 0]);
                acc2[2 * j + 1] = ffma2(hv2, w.y, acc2[2 * j + 1]);
            }
        }

        const float* alm = als + m * 64;
        const float* arm = ars + m * 64;
        float e_l = 0.0f, e_r = 0.0f;
        float4* fout = (float4*)&g_feat[m][(size_t)row * 64];
        float4* zout = (float4*)&g_z[2 * type + m][(size_t)row * 64];
        float4 z4 = make_float4(0.f, 0.f, 0.f, 0.f);
#pragma unroll
        for (int i = 0; i < 16; i++) {
            float a0, a1, a2, a3;
            unpack2(acc2[2 * i + 0], a0, a1);
            unpack2(acc2[2 * i + 1], a2, a3);
            e_l += a0 * alm[4 * i + 0] + a1 * alm[4 * i + 1]
                 + a2 * alm[4 * i + 2] + a3 * alm[4 * i + 3];
            e_r += a0 * arm[4 * i + 0] + a1 * arm[4 * i + 1]
                 + a2 * arm[4 * i + 2] + a3 * arm[4 * i + 3];
            fout[i] = make_float4(a0, a1, a2, a3);
            zout[i] = z4;
        }
        g_el[m][row] = e_l;
        g_er[m][row] = e_r;
        g_den[m][row] = 0.0f;
    }
}

// ---------------- K2: fused edge score + exp + segment sum (grid.y = m) -----
__global__ void k_edge_score(const int* __restrict__ src, const int* __restrict__ dst)
{
    int m = blockIdx.y;
    int i = blockIdx.x * blockDim.x + threadIdx.x;
    if (i >= EE) return;
    const int* srcm = src + (size_t)m * EE;
    const int* dstm = dst + (size_t)m * EE;
    int s = srcm[i], d = dstm[i];
    float e = g_el[m][s] + g_er[m][d];
    e = (e >= 0.0f) ? e : 0.2f * e;          // leaky_relu 0.2
    float ex = __expf(e);
    g_e[m][i] = ex;
    atomicAdd(&g_den[m][d], ex);
}

// ---------------- K3: alpha * feat[src] scatter-add into z (grid.y = m) -----
__global__ void __launch_bounds__(256) k_edge_aggr(
    const int* __restrict__ src, const int* __restrict__ dst, int type)
{
    int m = blockIdx.y;
    int t = blockIdx.x * 256 + threadIdx.x;
    int edge = t >> 4;
    int lane = t & 15;
    if (edge >= EE) return;
    const int* srcm = src + (size_t)m * EE;
    const int* dstm = dst + (size_t)m * EE;
    int s = srcm[edge], d = dstm[edge];
    float alpha = g_e[m][edge] / (g_den[m][d] + 1e-9f);
    float4 f = *(const float4*)&g_feat[m][(size_t)s * 64 + lane * 4];
    float4 v = make_float4(f.x * alpha, f.y * alpha, f.z * alpha, f.w * alpha);
    float* zp = &g_z[2 * type + m][(size_t)d * 64 + lane * 4];
    asm volatile("red.global.add.v4.f32 [%0], {%1,%2,%3,%4};"
                 :: "l"(zp), "f"(v.x), "f"(v.y), "f"(v.z), "f"(v.w)
                 : "memory");
}

// ---------------- K4: semantic attention logits (bf16 HFMA2 inner product) --
__global__ void __launch_bounds__(128) k_sem(
    const float* __restrict__ uW1, const float* __restrict__ ub1,
    const float* __restrict__ uW2, const float* __restrict__ ugb,
    const float* __restrict__ iW1, const float* __restrict__ ib1,
    const float* __restrict__ iW2, const float* __restrict__ igb)
{
    __shared__ __align__(16) __nv_bfloat162 zs0[4][32];
    __shared__ __align__(16) __nv_bfloat162 zs1[4][32];
    __shared__ float bsh[128];     // [metapath0 64 | metapath1 64]
    __shared__ float redbuf[8];

    int t = blockIdx.y;
    const float* W1 = t ? iW1 : uW1;
    const float* b1 = t ? ib1 : ub1;
    const float* W2 = t ? iW2 : uW2;
    const float* gb = t ? igb : ugb;
    const float* z0 = g_z[2 * t];
    const float* z1 = g_z[2 * t + 1];

    int h = threadIdx.x;
    bsh[h] = gb[h];

    // W1 column h as 32 bf16x2 pairs (consecutive k)
    __nv_bfloat162 wp[32];
#pragma unroll
    for (int k2 = 0; k2 < 32; k2++)
        wp[k2] = __floats2bfloat162_rn(W1[(size_t)(2 * k2) * 128 + h],
                                       W1[(size_t)(2 * k2 + 1) * 128 + h]);
    float bh = b1[h];

    int r = h >> 5;          // staging row 0..3
    int c2 = h & 31;         // staging bf16x2 index

    float s0 = 0.0f, s1 = 0.0f;
    const int NCHUNK = NN / 4;   // 25000
    for (int c = blockIdx.x; c < NCHUNK; c += gridDim.x) {
        int row = c * 4 + r;
        float2 p0 = ((const float2*)(z0 + (size_t)row * 64))[c2];
        float2 p1 = ((const float2*)(z1 + (size_t)row * 64))[c2];
        __syncthreads();   // previous chunk's compute done before overwrite
        zs0[r][c2] = __floats2bfloat162_rn(elu_fast(p0.x + bsh[2 * c2 + 0]),
                                           elu_fast(p0.y + bsh[2 * c2 + 1]));
        zs1[r][c2] = __floats2bfloat162_rn(elu_fast(p1.x + bsh[64 + 2 * c2 + 0]),
                                           elu_fast(p1.y + bsh[64 + 2 * c2 + 1]));
        __syncthreads();

#pragma unroll
        for (int rr = 0; rr < 4; rr++) {
            __nv_bfloat162 zero2 = __floats2bfloat162_rn(0.f, 0.f);
            __nv_bfloat162 a0a = zero2, a0b = zero2, a1a = zero2, a1b = zero2;
            const uint4* q0 = (const uint4*)zs0[rr];
            const uint4* q1 = (const uint4*)zs1[rr];
#pragma unroll
            for (int j = 0; j < 8; j++) {
                uint4 x0 = q0[j];
                uint4 x1 = q1[j];
                a0a = __hfma2(u2bf(x0.x), wp[4 * j + 0], a0a);
                a0b = __hfma2(u2bf(x0.y), wp[4 * j + 1], a0b);
                a0a = __hfma2(u2bf(x0.z), wp[4 * j + 2], a0a);
                a0b = __hfma2(u2bf(x0.w), wp[4 * j + 3], a0b);
                a1a = __hfma2(u2bf(x1.x), wp[4 * j + 0], a1a);
                a1b = __hfma2(u2bf(x1.y), wp[4 * j + 1], a1b);
                a1a = __hfma2(u2bf(x1.z), wp[4 * j + 2], a1a);
                a1b = __hfma2(u2bf(x1.w), wp[4 * j + 3], a1b);
            }
            float2 f0a = __bfloat1622float2(a0a);
            float2 f0b = __bfloat1622float2(a0b);
            float2 f1a = __bfloat1622float2(a1a);
            float2 f1b = __bfloat1622float2(a1b);
            s0 += tanh_fast(f0a.x + f0a.y + f0b.x + f0b.y + bh);
            s1 += tanh_fast(f1a.x + f1a.y + f1b.x + f1b.y + bh);
        }
    }

    float v2 = W2[h];
    s0 *= v2; s1 *= v2;
#pragma unroll
    for (int off = 16; off > 0; off >>= 1) {
        s0 += __shfl_xor_sync(0xffffffffu, s0, off);
        s1 += __shfl_xor_sync(0xffffffffu, s1, off);
    }
    int w = h >> 5;
    if ((h & 31) == 0) { redbuf[w] = s0; redbuf[4 + w] = s1; }
    __syncthreads();
    if (h == 0) {
        float t0 = redbuf[0] + redbuf[1] + redbuf[2] + redbuf[3];
        float t1 = redbuf[4] + redbuf[5] + redbuf[6] + redbuf[7];
        atomicAdd(&g_w[2 * t + 0], t0);
        atomicAdd(&g_w[2 * t + 1], t1);
    }
}

// ---------------- K5: beta = softmax(w / NN) over metapaths -----------------
__global__ void k_beta()
{
    if (threadIdx.x != 0 || blockIdx.x != 0) return;
    for (int t = 0; t < 2; t++) {
        float w0 = g_w[2 * t] * (1.0f / NN);
        float w1 = g_w[2 * t + 1] * (1.0f / NN);
        float m = fmaxf(w0, w1);
        float e0 = __expf(w0 - m), e1 = __expf(w1 - m);
        float inv = 1.0f / (e0 + e1);
        g_beta[2 * t + 0] = e0 * inv;
        g_beta[2 * t + 1] = e1 * inv;
    }
}

// ---------------- K6: gather + bias/ELU + beta-combine + GEMM + ReLU + LN ----
__global__ void __launch_bounds__(256) k_final(
    const int* __restrict__ user_idx, const int* __restrict__ item_idx,
    const int* __restrict__ neg_idx,
    const float* __restrict__ u_gb, const float* __restrict__ i_gb,
    const float* __restrict__ userW, const float* __restrict__ userb,
    const float* __restrict__ itemW, const float* __restrict__ itemb,
    const float* __restrict__ ln_g, const float* __restrict__ ln_b,
    float* __restrict__ out)
{
    __shared__ float Ws[4096];
    __shared__ float bs[64], gs[64], lbs[64];
    __shared__ float gb0[64], gb1[64];
    __shared__ float embs[4][64];
    __shared__ float red[4][2];

    int tid = threadIdx.x;
    int tx = tid & 63, ty = tid >> 6;
    int r0 = blockIdx.x * 4;
    bool isUser = (r0 < BB);                 // uniform per block (BB % 4 == 0)
    const float* W    = isUser ? userW : itemW;
    const float* bias = isUser ? userb : itemb;
    const float* gbm  = isUser ? u_gb : i_gb;

    for (int i = tid; i < 4096; i += 256) Ws[i] = W[i];
    if (tid < 64) {
        bs[tid] = bias[tid]; gs[tid] = ln_g[tid]; lbs[tid] = ln_b[tid];
        gb0[tid] = gbm[tid]; gb1[tid] = gbm[64 + tid];
    }

    int r = r0 + ty;
    int type, idx;
    if (r < BB)            { type = 0; idx = user_idx[r]; }
    else if (r < 2 * BB)   { type = 1; idx = item_idx[r - BB]; }
    else                   { type = 1; idx = neg_idx[r - 2 * BB]; }

    float b0 = g_beta[2 * type], b1 = g_beta[2 * type + 1];
    __syncthreads();
    float zr0 = g_z[2 * type][(size_t)idx * 64 + tx] + gb0[tx];
    float zr1 = g_z[2 * type + 1][(size_t)idx * 64 + tx] + gb1[tx];
    float emb = b0 * elu_fast(zr0) + b1 * elu_fast(zr1);
    embs[ty][tx] = emb;
    __syncthreads();

    float y = bs[tx];
#pragma unroll 16
    for (int k = 0; k < 64; k++) y += embs[ty][k] * Ws[k * 64 + tx];
    y = fmaxf(y, 0.0f);

    float s = y;
#pragma unroll
    for (int off = 16; off > 0; off >>= 1) s += __shfl_xor_sync(0xffffffffu, s, off);
    int half = tx >> 5;
    if ((tx & 31) == 0) red[ty][half] = s;
    __syncthreads();
    float mu = (red[ty][0] + red[ty][1]) * (1.0f / 64.0f);
    float dv = y - mu;
    float s2 = dv * dv;
#pragma unroll
    for (int off = 16; off > 0; off >>= 1) s2 += __shfl_xor_sync(0xffffffffu, s2, off);
    __syncthreads();
    if ((tx & 31) == 0) red[ty][half] = s2;
    __syncthreads();
    float var = (red[ty][0] + red[ty][1]) * (1.0f / 64.0f);
    float o = gs[tx] * dv * rsqrtf(var + 1e-5f) + lbs[tx];
    out[(size_t)r * 64 + tx] = o;
}

// ---------------- host ------------------------------------------------------
extern "C" void kernel_launch(void* const* d_in, const int* in_sizes, int n_in,
                              void* d_out, int out_size)
{
    const int*   user_idx  = (const int*)d_in[0];
    const int*   item_idx  = (const int*)d_in[1];
    const int*   neg_idx   = (const int*)d_in[2];
    const float* user_feat = (const float*)d_in[3];
    const float* item_feat = (const float*)d_in[4];
    const int*   u_src = (const int*)d_in[5];
    const int*   u_dst = (const int*)d_in[6];
    const int*   i_src = (const int*)d_in[7];
    const int*   i_dst = (const int*)d_in[8];
    const float* u_W  = (const float*)d_in[9];
    const float* u_al = (const float*)d_in[10];
    const float* u_ar = (const float*)d_in[11];
    const float* u_b  = (const float*)d_in[12];
    const float* i_W  = (const float*)d_in[13];
    const float* i_al = (const float*)d_in[14];
    const float* i_ar = (const float*)d_in[15];
    const float* i_b  = (const float*)d_in[16];
    const float* u_saW1 = (const float*)d_in[17];
    const float* u_sab1 = (const float*)d_in[18];
    const float* u_saW2 = (const float*)d_in[19];
    const float* i_saW1 = (const float*)d_in[20];
    const float* i_sab1 = (const float*)d_in[21];
    const float* i_saW2 = (const float*)d_in[22];
    const float* userW = (const float*)d_in[23];
    const float* userb = (const float*)d_in[24];
    const float* itemW = (const float*)d_in[25];
    const float* itemb = (const float*)d_in[26];
    const float* ln_g  = (const float*)d_in[27];
    const float* ln_b  = (const float*)d_in[28];
    float* out = (float*)d_out;

    cudaFuncSetAttribute(k_gemm_feat,
                         cudaFuncAttributeMaxDynamicSharedMemorySize, K1_SMEM);

    const float* feats[2] = {user_feat, item_feat};
    const int*   srcs[2]  = {u_src, i_src};
    const int*   dsts[2]  = {u_dst, i_dst};
    const float* Wms[2]   = {u_W, i_W};
    const float* als[2]   = {u_al, i_al};
    const float* ars[2]   = {u_ar, i_ar};

    const int grid1 = (NN + 255) / 256;          // 391
    dim3 gridE((EE + 255) / 256, 2);             // 1954 x 2
    dim3 gridA((EE * 16) / 256, 2);              // 31250 x 2

    for (int t = 0; t < 2; t++) {
        k_gemm_feat<<<grid1, 256, K1_SMEM>>>(feats[t], Wms[t], als[t], ars[t], t);
        k_edge_score<<<gridE, 256>>>(srcs[t], dsts[t]);
        k_edge_aggr<<<gridA, 256>>>(srcs[t], dsts[t], t);
    }

    dim3 semGrid(1024, 2);
    k_sem<<<semGrid, 128>>>(u_saW1, u_sab1, u_saW2, u_b,
                            i_saW1, i_sab1, i_saW2, i_b);
    k_beta<<<1, 1>>>();
    k_final<<<(3 * BB) / 4, 256>>>(user_idx, item_idx, neg_idx, u_b, i_b,
                                   userW, userb, itemW, itemb, ln_g, ln_b, out);
}